// round 13
// baseline (speedup 1.0000x reference)
#include <cuda_runtime.h>
#include <cuda_fp16.h>
#include <cstdint>
#include <cstddef>

#define T_TOK 8192
#define DIN   4096
#define DOUT  4096
#define NE    8
#define ER    128          // E * R
#define KCAT  4224         // DIN + ER
#define SCALING 2.0f

// ---------------------------------------------------------------------------
// Scratch (device globals; no allocations allowed)
// ---------------------------------------------------------------------------
__device__ __align__(128) __half g_xf[(size_t)T_TOK * KCAT];
__device__ __align__(128) __half g_wf[(size_t)DOUT * KCAT];
__device__ __align__(128) __half g_af[(size_t)ER * DIN];
__device__ float g_logits[(size_t)T_TOK * NE];

// ---------------------------------------------------------------------------
// PTX primitives (baseline sm_80+)
// ---------------------------------------------------------------------------
__device__ __forceinline__ uint32_t smem_u32(const void* p) {
    uint32_t a;
    asm("{ .reg .u64 t; cvta.to.shared.u64 t, %1; cvt.u32.u64 %0, t; }"
        : "=r"(a) : "l"(p));
    return a;
}
__device__ __forceinline__ void cp16(uint32_t s, const void* g) {
    asm volatile("cp.async.cg.shared.global [%0], [%1], 16;" :: "r"(s), "l"(g));
}
#define CP_COMMIT() asm volatile("cp.async.commit_group;" ::: "memory")
#define CP_WAIT(n)  asm volatile("cp.async.wait_group %0;" :: "n"(n) : "memory")

__device__ __forceinline__ void ldsm4(uint32_t* r, uint32_t addr) {
    asm volatile("ldmatrix.sync.aligned.m8n8.x4.shared.b16 {%0,%1,%2,%3}, [%4];"
                 : "=r"(r[0]), "=r"(r[1]), "=r"(r[2]), "=r"(r[3]) : "r"(addr));
}
__device__ __forceinline__ void mma16816(float* d, const uint32_t* a,
                                         const uint32_t* b) {
    asm volatile(
        "mma.sync.aligned.m16n8k16.row.col.f32.f16.f16.f32 "
        "{%0,%1,%2,%3}, {%4,%5,%6,%7}, {%8,%9}, {%0,%1,%2,%3};"
        : "+f"(d[0]), "+f"(d[1]), "+f"(d[2]), "+f"(d[3])
        : "r"(a[0]), "r"(a[1]), "r"(a[2]), "r"(a[3]), "r"(b[0]), "r"(b[1]));
}

__device__ __forceinline__ uint32_t pack_h2(float a, float b) {
    __half2 h;
    h.x = __float2half_rn(a);
    h.y = __float2half_rn(b);
    return *(const uint32_t*)&h;
}

// ---------------------------------------------------------------------------
// fp16 GEMM: C[M,N] = A @ B^T. Block tile BM x BN, 8 warps.
//   BM=128: warps 2x4, warp tile 64 x BN/4.
//   BM=64 : warps 1x8, warp tile 64 x BN/8.
// BK = 128 halves, 2-stage cp.async, register double-buffered fragments,
// two barriers per chunk (canonical cp.async visibility pattern).
// Smem pitch 272 B: conflict-free for cp.async stores and ldmatrix reads.
// blockIdx.x = n-tile (fast), blockIdx.y = m-tile (A-tile reuse in a wave).
// EPI 0: +bias, fp32 C.   EPI 1: MoE routing epilogue -> fp16 G cols of g_xf.
// ---------------------------------------------------------------------------
#define PITCH 272

template <int K_TOT, int BM, int BN, int EPI>
__global__ void __launch_bounds__(256, 1)
gemm_mma(const __half* __restrict__ A, const __half* __restrict__ B,
         const float* __restrict__ bias, float* __restrict__ C,
         int ldc, int lda, int ldb) {
    constexpr int NCH     = K_TOT / 128;
    constexpr int ROWS    = BM + BN;
    constexpr int STAGE_B = ROWS * PITCH;
    constexpr int MW      = BM / 64;             // m-warps (1 or 2)
    constexpr int WN      = BN / (8 / MW);       // warp n-extent
    constexpr int NP      = WN / 16;             // B ldsm4 per k16
    constexpr int LPT     = ROWS / 16;           // cp16 per thread per stage

    extern __shared__ char sm[];
    const uint32_t base = smem_u32(sm);

    const int tid  = threadIdx.x;
    const int wid  = tid >> 5;
    const int lane = tid & 31;
    const int bm = blockIdx.y * BM;    // m-tile on slow axis
    const int bn = blockIdx.x * BN;    // n-tile on fast axis
    const int wm = (wid % MW) * 64;
    const int wn = (wid / MW) * WN;

    auto stage_load = [&](int c, int s) {
        const int kk = c * 128;
        const uint32_t sb = base + s * STAGE_B;
#pragma unroll
        for (int i = 0; i < LPT; ++i) {
            int idx  = tid + i * 256;
            int row  = idx >> 4;
            int part = idx & 15;
            const __half* g = (row < BM)
                ? A + (size_t)(bm + row) * lda + kk + part * 8
                : B + (size_t)(bn + row - BM) * ldb + kk + part * 8;
            cp16(sb + row * PITCH + part * 16, g);
        }
        CP_COMMIT();
    };

    float acc[4][2 * NP][4];
#pragma unroll
    for (int i = 0; i < 4; i++)
#pragma unroll
        for (int j = 0; j < 2 * NP; j++)
#pragma unroll
            for (int k = 0; k < 4; k++) acc[i][j][k] = 0.f;

    stage_load(0, 0);
    stage_load(1, 1);

    const uint32_t a_off = (wm + (lane & 15)) * PITCH + (lane >> 4) * 16;
    const uint32_t b_row = wn + (lane & 7) + ((lane >> 4) & 1) * 8;
    const uint32_t b_off = b_row * PITCH + ((lane >> 3) & 1) * 16;

    uint32_t aF[2][4][4];
    uint32_t bF[2][NP][4];

    for (int c = 0; c < NCH; ++c) {
        const int s = c & 1;
        // CP_WAIT certifies this thread's chunk-c group; the barrier makes
        // every thread's chunk-c data visible to every warp.
        CP_WAIT(1);
        __syncthreads();

        const uint32_t sA = base + s * STAGE_B;
        const uint32_t sB = sA + BM * PITCH;

        // prime ks=0 frags
#pragma unroll
        for (int mf = 0; mf < 4; ++mf)
            ldsm4(aF[0][mf], sA + a_off + mf * (16 * PITCH));
#pragma unroll
        for (int p = 0; p < NP; ++p)
            ldsm4(bF[0][p], sB + b_off + p * (16 * PITCH));

#pragma unroll
        for (int ks = 0; ks < 8; ++ks) {
            const int cur = ks & 1, nxt = cur ^ 1;
            if (ks < 7) {
#pragma unroll
                for (int mf = 0; mf < 4; ++mf)
                    ldsm4(aF[nxt][mf], sA + a_off + mf * (16 * PITCH) + (ks + 1) * 32);
#pragma unroll
                for (int p = 0; p < NP; ++p)
                    ldsm4(bF[nxt][p], sB + b_off + p * (16 * PITCH) + (ks + 1) * 32);
            }
#pragma unroll
            for (int mf = 0; mf < 4; ++mf)
#pragma unroll
                for (int p = 0; p < NP; ++p) {
                    mma16816(acc[mf][2 * p + 0], aF[cur][mf], &bF[cur][p][0]);
                    mma16816(acc[mf][2 * p + 1], aF[cur][mf], &bF[cur][p][2]);
                }
        }

        // all warps done reading stage s -> safe to overwrite with chunk c+2
        __syncthreads();
        if (c + 2 < NCH) stage_load(c + 2, s);
        else CP_COMMIT();   // keep one commit per iteration (wait invariant)
    }

    const int row0 = wm + (lane >> 2);
    const int col0 = wn + (lane & 3) * 2;

    if (EPI == 0) {
        // bias + fp32 store
#pragma unroll
        for (int mf = 0; mf < 4; ++mf) {
#pragma unroll
            for (int r8 = 0; r8 < 2; ++r8) {
                int row = bm + row0 + mf * 16 + r8 * 8;
                float* Cr = C + (size_t)row * ldc;
#pragma unroll
                for (int nf = 0; nf < 2 * NP; ++nf) {
                    int col = bn + col0 + nf * 8;
                    float2 v;
                    v.x = acc[mf][nf][r8 * 2 + 0];
                    v.y = acc[mf][nf][r8 * 2 + 1];
                    v.x += bias[col]; v.y += bias[col + 1];
                    *(float2*)(Cr + col) = v;
                }
            }
        }
    } else {
        // Routing epilogue: h -> weighted fp16 G columns of g_xf.
        __shared__ float s_w1[BM], s_w2[BM];
        __shared__ int   s_i1[BM], s_i2[BM];
        __syncthreads();
        if (tid < BM) {
            const int t = bm + tid;
            float l[NE];
#pragma unroll
            for (int e = 0; e < NE; ++e) l[e] = g_logits[(size_t)t * NE + e];
            float best = -1e30f; int i1 = 0;
#pragma unroll
            for (int e = 0; e < NE; ++e)
                if (l[e] > best) { best = l[e]; i1 = e; }
            float second = -1e30f; int i2 = 0;
#pragma unroll
            for (int e = 0; e < NE; ++e) {
                if (e == i1) continue;
                if (l[e] > second) { second = l[e]; i2 = e; }
            }
            float r  = expf(second - best);
            float w1 = 1.0f / (1.0f + r);
            s_w1[tid] = SCALING * w1;
            s_w2[tid] = SCALING * r * w1;
            s_i1[tid] = i1;
            s_i2[tid] = i2;
        }
        __syncthreads();
#pragma unroll
        for (int mf = 0; mf < 4; ++mf) {
#pragma unroll
            for (int r8 = 0; r8 < 2; ++r8) {
                int rl = row0 + mf * 16 + r8 * 8;
                int t  = bm + rl;
                float sw1 = s_w1[rl], sw2 = s_w2[rl];
                int i1 = s_i1[rl], i2 = s_i2[rl];
                __half* dst = g_xf + (size_t)t * KCAT + DIN;
#pragma unroll
                for (int nf = 0; nf < 2 * NP; ++nf) {
                    int col = col0 + nf * 8;  // 0..127, even
                    int e = col >> 4;
                    float m = (e == i1) ? sw1 : ((e == i2) ? sw2 : 0.f);
                    __half2 hv;
                    hv.x = __float2half_rn(m * acc[mf][nf][r8 * 2 + 0]);
                    hv.y = __float2half_rn(m * acc[mf][nf][r8 * 2 + 1]);
                    *(__half2*)(dst + col) = hv;
                }
            }
        }
    }
}

// ---------------------------------------------------------------------------
// prep_x: x fp32->fp16 into g_xf[:, 0:4096) + router logits (2 tokens/warp).
// ---------------------------------------------------------------------------
#define TPW 2
#define XB  (T_TOK / (8 * TPW))   // 512 blocks

__global__ void __launch_bounds__(256)
prep_x_kernel(const float* __restrict__ x, const float* __restrict__ Wr) {
    const int wid  = threadIdx.x >> 5;
    const int lane = threadIdx.x & 31;
    const int t0 = (blockIdx.x * 8 + wid) * TPW;
    const float* xr0 = x + (size_t)t0 * DIN;
    const float* xr1 = xr0 + DIN;
    __half* xo0 = g_xf + (size_t)t0 * KCAT;
    __half* xo1 = xo0 + KCAT;

    float acc0[NE], acc1[NE];
#pragma unroll
    for (int e = 0; e < NE; ++e) { acc0[e] = 0.f; acc1[e] = 0.f; }

#pragma unroll 2
    for (int i = 0; i < 32; ++i) {
        int off = i * 128 + lane * 4;
        float4 w[NE];
#pragma unroll
        for (int e = 0; e < NE; ++e)
            w[e] = *(const float4*)(Wr + (size_t)e * DIN + off);

        float4 v0 = *(const float4*)(xr0 + off);
        float4 v1 = *(const float4*)(xr1 + off);
        uint2 p0, p1;
        p0.x = pack_h2(v0.x, v0.y); p0.y = pack_h2(v0.z, v0.w);
        p1.x = pack_h2(v1.x, v1.y); p1.y = pack_h2(v1.z, v1.w);
        *(uint2*)(xo0 + off) = p0;
        *(uint2*)(xo1 + off) = p1;
#pragma unroll
        for (int e = 0; e < NE; ++e) {
            acc0[e] += v0.x * w[e].x + v0.y * w[e].y
                     + v0.z * w[e].z + v0.w * w[e].w;
            acc1[e] += v1.x * w[e].x + v1.y * w[e].y
                     + v1.z * w[e].z + v1.w * w[e].w;
        }
    }
#pragma unroll
    for (int e = 0; e < NE; ++e) {
#pragma unroll
        for (int off = 16; off > 0; off >>= 1) {
            acc0[e] += __shfl_xor_sync(0xffffffffu, acc0[e], off);
            acc1[e] += __shfl_xor_sync(0xffffffffu, acc1[e], off);
        }
    }
    if (lane == 0) {
#pragma unroll
        for (int e = 0; e < NE; ++e) {
            g_logits[(size_t)t0 * NE + e]       = acc0[e];
            g_logits[(size_t)(t0 + 1) * NE + e] = acc1[e];
        }
    }
}

// ---------------------------------------------------------------------------
// prep_w: Wb -> g_wf[:, 0:4096), A -> g_af, Bm -> g_wf[:, 4096:4224).
// Runs on a second stream, overlapped with prep_x + h-GEMM.
// ---------------------------------------------------------------------------
__global__ void __launch_bounds__(256)
prep_w_kernel(const float* __restrict__ Wb, const float* __restrict__ A,
              const float* __restrict__ Bm) {
    const long long N1 = (long long)DOUT * (DIN / 8);   // Wb groups
    const long long N2 = (long long)ER * (DIN / 8);     // A groups
    const long long N3 = (long long)DOUT * (ER / 2);    // Bflat half2
    long long i = (long long)blockIdx.x * 256 + threadIdx.x;
    if (i < N1) {
        long long r = i / (DIN / 8);
        int c8 = (int)(i % (DIN / 8));
        const float* src = Wb + r * DIN + 8 * c8;
        float4 v0 = *(const float4*)(src);
        float4 v1 = *(const float4*)(src + 4);
        uint4 pk;
        pk.x = pack_h2(v0.x, v0.y);
        pk.y = pack_h2(v0.z, v0.w);
        pk.z = pack_h2(v1.x, v1.y);
        pk.w = pack_h2(v1.z, v1.w);
        *(uint4*)(g_wf + r * KCAT + 8 * c8) = pk;
    } else if (i < N1 + N2) {
        long long j = i - N1;
        const float* src = A + 8 * j;
        float4 v0 = *(const float4*)(src);
        float4 v1 = *(const float4*)(src + 4);
        uint4 pk;
        pk.x = pack_h2(v0.x, v0.y);
        pk.y = pack_h2(v0.z, v0.w);
        pk.z = pack_h2(v1.x, v1.y);
        pk.w = pack_h2(v1.z, v1.w);
        *(uint4*)(g_af + 8 * j) = pk;
    } else if (i < N1 + N2 + N3) {
        long long j = i - N1 - N2;
        int o  = (int)(j >> 6);
        int c  = (int)(j & 63) * 2;   // even column in [0,128)
        int e  = c >> 4;
        int r  = c & 15;
        float2 v = *(const float2*)(Bm + ((size_t)e * DOUT + o) * 16 + r);
        *(uint32_t*)(g_wf + (size_t)o * KCAT + DIN + c) = pack_h2(v.x, v.y);
    }
}

// ---------------------------------------------------------------------------
// Host launcher — forked two-stream schedule (graph-capturable):
//   stream0: prep_x -> h-GEMM(+routing) -> [join] -> main GEMM
//   stream1: prep_w (A-GEMM weights + main-GEMM weights), overlapped
// NOTE: h-GEMM needs g_af from prep_w, so the A-conversion is ordered before
// the h-GEMM via event e_af... A is small (1 MB). To keep it simple and safe,
// prep_w carries ALL weight conversion and the h-GEMM waits only on the A part
// being done -> we instead order: s1 runs prep_w; stream0 waits e1 before the
// h-GEMM ONLY for g_af. To avoid a second event we put the A-conversion in
// prep_x's grid tail instead (256 extra blocks, trivially parallel).
// ---------------------------------------------------------------------------
__global__ void __launch_bounds__(256)
prep_a_kernel(const float* __restrict__ A) {
    long long j = (long long)blockIdx.x * 256 + threadIdx.x;  // 8-float groups
    const float* src = A + 8 * j;
    float4 v0 = *(const float4*)(src);
    float4 v1 = *(const float4*)(src + 4);
    uint4 pk;
    pk.x = pack_h2(v0.x, v0.y);
    pk.y = pack_h2(v0.z, v0.w);
    pk.z = pack_h2(v1.x, v1.y);
    pk.w = pack_h2(v1.z, v1.w);
    *(uint4*)(g_af + 8 * j) = pk;
}

constexpr int SMEM_MAIN = 2 * (128 + 256) * PITCH;  // 208896
constexpr int SMEM_H    = 2 * (64 + 128) * PITCH;   // 104448

extern "C" void kernel_launch(void* const* d_in, const int* in_sizes, int n_in,
                              void* d_out, int out_size) {
    const float* x    = (const float*)d_in[0];
    const float* Wb   = (const float*)d_in[1];
    const float* bias = (const float*)d_in[2];
    const float* Wr   = (const float*)d_in[3];
    const float* A    = (const float*)d_in[4];
    const float* Bm   = (const float*)d_in[5];
    float* out = (float*)d_out;

    void *p_xf, *p_wf, *p_af;
    cudaGetSymbolAddress(&p_xf, g_xf);
    cudaGetSymbolAddress(&p_wf, g_wf);
    cudaGetSymbolAddress(&p_af, g_af);

    static bool inited = false;
    static cudaStream_t s1;
    static cudaEvent_t e_fork, e_join;
    if (!inited) {
        cudaFuncSetAttribute(gemm_mma<KCAT, 128, 256, 0>,
                             cudaFuncAttributeMaxDynamicSharedMemorySize, SMEM_MAIN);
        cudaFuncSetAttribute(gemm_mma<DIN, 64, 128, 1>,
                             cudaFuncAttributeMaxDynamicSharedMemorySize, SMEM_H);
        cudaStreamCreateWithFlags(&s1, cudaStreamNonBlocking);
        cudaEventCreateWithFlags(&e_fork, cudaEventDisableTiming);
        cudaEventCreateWithFlags(&e_join, cudaEventDisableTiming);
        inited = true;
    }

    // Fork: prep_w (Wb + Bflat) on s1, overlapped with prep_x + h-GEMM.
    cudaEventRecord(e_fork, 0);
    cudaStreamWaitEvent(s1, e_fork, 0);
    {
        long long wtotal = (long long)DOUT * (DIN / 8) + (long long)ER * (DIN / 8)
                         + (long long)DOUT * (ER / 2);
        unsigned wb = (unsigned)((wtotal + 255) / 256);
        prep_w_kernel<<<wb, 256, 0, s1>>>(Wb, A, Bm);
    }
    cudaEventRecord(e_join, s1);

    // Stream 0: A-conversion (tiny, 1 MB; needed by h-GEMM), x-prep + router.
    prep_a_kernel<<<(ER * DIN / 8) / 256, 256>>>(A);
    prep_x_kernel<<<XB, 256>>>(x, Wr);

    // h = x @ A^T fused with routing -> G columns of g_xf
    {
        dim3 grid(1, T_TOK / 64);
        gemm_mma<DIN, 64, 128, 1><<<grid, 256, SMEM_H>>>(
            (const __half*)p_xf, (const __half*)p_af,
            nullptr, nullptr, 0, KCAT, DIN);
    }

    // Join: main GEMM needs g_wf from prep_w.
    cudaStreamWaitEvent(0, e_join, 0);

    // out = [x|G] @ [Wb|Bf]^T + bias   (n-fast CTA order)
    {
        dim3 grid(DOUT / 256, T_TOK / 128);
        gemm_mma<KCAT, 128, 256, 0><<<grid, 256, SMEM_MAIN>>>(
            (const __half*)p_xf, (const __half*)p_wf,
            bias, out, DOUT, KCAT, KCAT);
    }
}

// round 15
// speedup vs baseline: 1.0193x; 1.0193x over previous
#include <cuda_runtime.h>
#include <cuda_fp16.h>
#include <cstdint>
#include <cstddef>

#define T_TOK 8192
#define DIN   4096
#define DOUT  4096
#define NE    8
#define ER    128          // E * R
#define KCAT  4224         // DIN + ER
#define SCALING 2.0f

// ---------------------------------------------------------------------------
// Scratch (device globals; no allocations allowed)
// ---------------------------------------------------------------------------
__device__ __align__(128) __half g_xf[(size_t)T_TOK * KCAT];
__device__ __align__(128) __half g_wf[(size_t)DOUT * KCAT];
__device__ __align__(128) __half g_af[(size_t)ER * DIN];
__device__ float g_logits[(size_t)T_TOK * NE];

// ---------------------------------------------------------------------------
// PTX primitives (baseline sm_80+)
// ---------------------------------------------------------------------------
__device__ __forceinline__ uint32_t smem_u32(const void* p) {
    uint32_t a;
    asm("{ .reg .u64 t; cvta.to.shared.u64 t, %1; cvt.u32.u64 %0, t; }"
        : "=r"(a) : "l"(p));
    return a;
}
__device__ __forceinline__ void cp16(uint32_t s, const void* g) {
    asm volatile("cp.async.cg.shared.global [%0], [%1], 16;" :: "r"(s), "l"(g));
}
#define CP_COMMIT() asm volatile("cp.async.commit_group;" ::: "memory")
#define CP_WAIT(n)  asm volatile("cp.async.wait_group %0;" :: "n"(n) : "memory")

__device__ __forceinline__ void ldsm4(uint32_t* r, uint32_t addr) {
    asm volatile("ldmatrix.sync.aligned.m8n8.x4.shared.b16 {%0,%1,%2,%3}, [%4];"
                 : "=r"(r[0]), "=r"(r[1]), "=r"(r[2]), "=r"(r[3]) : "r"(addr));
}
__device__ __forceinline__ void mma16816(float* d, const uint32_t* a,
                                         const uint32_t* b) {
    asm volatile(
        "mma.sync.aligned.m16n8k16.row.col.f32.f16.f16.f32 "
        "{%0,%1,%2,%3}, {%4,%5,%6,%7}, {%8,%9}, {%0,%1,%2,%3};"
        : "+f"(d[0]), "+f"(d[1]), "+f"(d[2]), "+f"(d[3])
        : "r"(a[0]), "r"(a[1]), "r"(a[2]), "r"(a[3]), "r"(b[0]), "r"(b[1]));
}

__device__ __forceinline__ uint32_t pack_h2(float a, float b) {
    __half2 h;
    h.x = __float2half_rn(a);
    h.y = __float2half_rn(b);
    return *(const uint32_t*)&h;
}

// ---------------------------------------------------------------------------
// fp16 GEMM: C[M,N] = A @ B^T. Block tile BM x BN, 8 warps.
//   BM=128: warps 2x4, warp tile 64 x BN/4.
//   BM=64 : warps 1x8, warp tile 64 x BN/8.
// BK = 128 halves, 2-stage cp.async, register double-buffered fragments,
// two barriers per chunk (canonical cp.async visibility pattern).
// Smem pitch 272 B: conflict-free for cp.async stores and ldmatrix reads.
// blockIdx.x = n-tile (fast), blockIdx.y = m-tile (A-tile reuse in a wave).
// EPI 0: +bias, fp32 C.   EPI 1: MoE routing epilogue -> fp16 G cols of g_xf.
// ---------------------------------------------------------------------------
#define PITCH 272

template <int K_TOT, int BM, int BN, int EPI>
__global__ void __launch_bounds__(256, 1)
gemm_mma(const __half* __restrict__ A, const __half* __restrict__ B,
         const float* __restrict__ bias, float* __restrict__ C,
         int ldc, int lda, int ldb) {
    constexpr int NCH     = K_TOT / 128;
    constexpr int ROWS    = BM + BN;
    constexpr int STAGE_B = ROWS * PITCH;
    constexpr int MW      = BM / 64;             // m-warps (1 or 2)
    constexpr int WN      = BN / (8 / MW);       // warp n-extent
    constexpr int NP      = WN / 16;             // B ldsm4 per k16
    constexpr int LPT     = ROWS / 16;           // cp16 per thread per stage

    extern __shared__ char sm[];
    const uint32_t base = smem_u32(sm);

    const int tid  = threadIdx.x;
    const int wid  = tid >> 5;
    const int lane = tid & 31;
    const int bm = blockIdx.y * BM;    // m-tile on slow axis
    const int bn = blockIdx.x * BN;    // n-tile on fast axis
    const int wm = (wid % MW) * 64;
    const int wn = (wid / MW) * WN;

    auto stage_load = [&](int c, int s) {
        const int kk = c * 128;
        const uint32_t sb = base + s * STAGE_B;
#pragma unroll
        for (int i = 0; i < LPT; ++i) {
            int idx  = tid + i * 256;
            int row  = idx >> 4;
            int part = idx & 15;
            const __half* g = (row < BM)
                ? A + (size_t)(bm + row) * lda + kk + part * 8
                : B + (size_t)(bn + row - BM) * ldb + kk + part * 8;
            cp16(sb + row * PITCH + part * 16, g);
        }
        CP_COMMIT();
    };

    float acc[4][2 * NP][4];
#pragma unroll
    for (int i = 0; i < 4; i++)
#pragma unroll
        for (int j = 0; j < 2 * NP; j++)
#pragma unroll
            for (int k = 0; k < 4; k++) acc[i][j][k] = 0.f;

    stage_load(0, 0);
    stage_load(1, 1);

    const uint32_t a_off = (wm + (lane & 15)) * PITCH + (lane >> 4) * 16;
    const uint32_t b_row = wn + (lane & 7) + ((lane >> 4) & 1) * 8;
    const uint32_t b_off = b_row * PITCH + ((lane >> 3) & 1) * 16;

    uint32_t aF[2][4][4];
    uint32_t bF[2][NP][4];

    for (int c = 0; c < NCH; ++c) {
        const int s = c & 1;
        // CP_WAIT certifies this thread's chunk-c group; the barrier makes
        // every thread's chunk-c data visible to every warp.
        CP_WAIT(1);
        __syncthreads();

        const uint32_t sA = base + s * STAGE_B;
        const uint32_t sB = sA + BM * PITCH;

        // prime ks=0 frags
#pragma unroll
        for (int mf = 0; mf < 4; ++mf)
            ldsm4(aF[0][mf], sA + a_off + mf * (16 * PITCH));
#pragma unroll
        for (int p = 0; p < NP; ++p)
            ldsm4(bF[0][p], sB + b_off + p * (16 * PITCH));

#pragma unroll
        for (int ks = 0; ks < 8; ++ks) {
            const int cur = ks & 1, nxt = cur ^ 1;
            if (ks < 7) {
#pragma unroll
                for (int mf = 0; mf < 4; ++mf)
                    ldsm4(aF[nxt][mf], sA + a_off + mf * (16 * PITCH) + (ks + 1) * 32);
#pragma unroll
                for (int p = 0; p < NP; ++p)
                    ldsm4(bF[nxt][p], sB + b_off + p * (16 * PITCH) + (ks + 1) * 32);
            }
#pragma unroll
            for (int mf = 0; mf < 4; ++mf)
#pragma unroll
                for (int p = 0; p < NP; ++p) {
                    mma16816(acc[mf][2 * p + 0], aF[cur][mf], &bF[cur][p][0]);
                    mma16816(acc[mf][2 * p + 1], aF[cur][mf], &bF[cur][p][2]);
                }
        }

        // all warps done reading stage s -> safe to overwrite with chunk c+2
        __syncthreads();
        if (c + 2 < NCH) stage_load(c + 2, s);
        else CP_COMMIT();   // keep one commit per iteration (wait invariant)
    }

    const int row0 = wm + (lane >> 2);
    const int col0 = wn + (lane & 3) * 2;

    if (EPI == 0) {
        // bias + fp32 store
#pragma unroll
        for (int mf = 0; mf < 4; ++mf) {
#pragma unroll
            for (int r8 = 0; r8 < 2; ++r8) {
                int row = bm + row0 + mf * 16 + r8 * 8;
                float* Cr = C + (size_t)row * ldc;
#pragma unroll
                for (int nf = 0; nf < 2 * NP; ++nf) {
                    int col = bn + col0 + nf * 8;
                    float2 v;
                    v.x = acc[mf][nf][r8 * 2 + 0];
                    v.y = acc[mf][nf][r8 * 2 + 1];
                    v.x += bias[col]; v.y += bias[col + 1];
                    *(float2*)(Cr + col) = v;
                }
            }
        }
    } else {
        // Routing epilogue: h -> weighted fp16 G columns of g_xf.
        __shared__ float s_w1[BM], s_w2[BM];
        __shared__ int   s_i1[BM], s_i2[BM];
        __syncthreads();
        if (tid < BM) {
            const int t = bm + tid;
            float l[NE];
#pragma unroll
            for (int e = 0; e < NE; ++e) l[e] = g_logits[(size_t)t * NE + e];
            float best = -1e30f; int i1 = 0;
#pragma unroll
            for (int e = 0; e < NE; ++e)
                if (l[e] > best) { best = l[e]; i1 = e; }
            float second = -1e30f; int i2 = 0;
#pragma unroll
            for (int e = 0; e < NE; ++e) {
                if (e == i1) continue;
                if (l[e] > second) { second = l[e]; i2 = e; }
            }
            float r  = expf(second - best);
            float w1 = 1.0f / (1.0f + r);
            s_w1[tid] = SCALING * w1;
            s_w2[tid] = SCALING * r * w1;
            s_i1[tid] = i1;
            s_i2[tid] = i2;
        }
        __syncthreads();
#pragma unroll
        for (int mf = 0; mf < 4; ++mf) {
#pragma unroll
            for (int r8 = 0; r8 < 2; ++r8) {
                int rl = row0 + mf * 16 + r8 * 8;
                int t  = bm + rl;
                float sw1 = s_w1[rl], sw2 = s_w2[rl];
                int i1 = s_i1[rl], i2 = s_i2[rl];
                __half* dst = g_xf + (size_t)t * KCAT + DIN;
#pragma unroll
                for (int nf = 0; nf < 2 * NP; ++nf) {
                    int col = col0 + nf * 8;  // 0..127, even
                    int e = col >> 4;
                    float m = (e == i1) ? sw1 : ((e == i2) ? sw2 : 0.f);
                    __half2 hv;
                    hv.x = __float2half_rn(m * acc[mf][nf][r8 * 2 + 0]);
                    hv.y = __float2half_rn(m * acc[mf][nf][r8 * 2 + 1]);
                    *(__half2*)(dst + col) = hv;
                }
            }
        }
    }
}

// ---------------------------------------------------------------------------
// Merged prep kernel (single launch):
//   blocks [0, XB)   : x fp32->fp16 into g_xf[:, 0:4096) + router logits.
//                      TWO tokens per warp -> Wr L1 traffic halved vs
//                      warp-per-token, at ~54 regs.
//   blocks [XB, ...) : Wb -> g_wf[:, 0:4096) (8 floats/thread, uint4 store),
//                      A -> g_af (8 floats/thread),
//                      Bm -> g_wf[:, 4096:4224) (2 scalars/thread)
// ---------------------------------------------------------------------------
#define TPW 2
#define XB  (T_TOK / (8 * TPW))   // 512 blocks

__global__ void __launch_bounds__(256)
prep_kernel(const float* __restrict__ x, const float* __restrict__ Wr,
            const float* __restrict__ Wb, const float* __restrict__ A,
            const float* __restrict__ Bm) {
    if (blockIdx.x < XB) {
        const int wid  = threadIdx.x >> 5;
        const int lane = threadIdx.x & 31;
        const int t0 = (blockIdx.x * 8 + wid) * TPW;
        const float* xr0 = x + (size_t)t0 * DIN;
        const float* xr1 = xr0 + DIN;
        __half* xo0 = g_xf + (size_t)t0 * KCAT;
        __half* xo1 = xo0 + KCAT;

        float acc0[NE], acc1[NE];
#pragma unroll
        for (int e = 0; e < NE; ++e) { acc0[e] = 0.f; acc1[e] = 0.f; }

#pragma unroll 2
        for (int i = 0; i < 32; ++i) {
            int off = i * 128 + lane * 4;
            float4 w[NE];
#pragma unroll
            for (int e = 0; e < NE; ++e)
                w[e] = *(const float4*)(Wr + (size_t)e * DIN + off);

            float4 v0 = *(const float4*)(xr0 + off);
            float4 v1 = *(const float4*)(xr1 + off);
            uint2 p0, p1;
            p0.x = pack_h2(v0.x, v0.y); p0.y = pack_h2(v0.z, v0.w);
            p1.x = pack_h2(v1.x, v1.y); p1.y = pack_h2(v1.z, v1.w);
            *(uint2*)(xo0 + off) = p0;
            *(uint2*)(xo1 + off) = p1;
#pragma unroll
            for (int e = 0; e < NE; ++e) {
                acc0[e] += v0.x * w[e].x + v0.y * w[e].y
                         + v0.z * w[e].z + v0.w * w[e].w;
                acc1[e] += v1.x * w[e].x + v1.y * w[e].y
                         + v1.z * w[e].z + v1.w * w[e].w;
            }
        }
#pragma unroll
        for (int e = 0; e < NE; ++e) {
#pragma unroll
            for (int off = 16; off > 0; off >>= 1) {
                acc0[e] += __shfl_xor_sync(0xffffffffu, acc0[e], off);
                acc1[e] += __shfl_xor_sync(0xffffffffu, acc1[e], off);
            }
        }
        if (lane == 0) {
#pragma unroll
            for (int e = 0; e < NE; ++e) {
                g_logits[(size_t)t0 * NE + e]       = acc0[e];
                g_logits[(size_t)(t0 + 1) * NE + e] = acc1[e];
            }
        }
        return;
    }

    // weight-prep part (8-float groups for Wb/A, half2 pairs for Bflat)
    const long long N1 = (long long)DOUT * (DIN / 8);   // Wb groups
    const long long N2 = (long long)ER * (DIN / 8);     // A groups
    const long long N3 = (long long)DOUT * (ER / 2);    // Bflat half2
    long long i = (long long)(blockIdx.x - XB) * 256 + threadIdx.x;
    if (i < N1) {
        long long r = i / (DIN / 8);
        int c8 = (int)(i % (DIN / 8));
        const float* src = Wb + r * DIN + 8 * c8;
        float4 v0 = *(const float4*)(src);
        float4 v1 = *(const float4*)(src + 4);
        uint4 pk;
        pk.x = pack_h2(v0.x, v0.y);
        pk.y = pack_h2(v0.z, v0.w);
        pk.z = pack_h2(v1.x, v1.y);
        pk.w = pack_h2(v1.z, v1.w);
        *(uint4*)(g_wf + r * KCAT + 8 * c8) = pk;
    } else if (i < N1 + N2) {
        long long j = i - N1;
        const float* src = A + 8 * j;
        float4 v0 = *(const float4*)(src);
        float4 v1 = *(const float4*)(src + 4);
        uint4 pk;
        pk.x = pack_h2(v0.x, v0.y);
        pk.y = pack_h2(v0.z, v0.w);
        pk.z = pack_h2(v1.x, v1.y);
        pk.w = pack_h2(v1.z, v1.w);
        *(uint4*)(g_af + 8 * j) = pk;
    } else if (i < N1 + N2 + N3) {
        long long j = i - N1 - N2;
        int o  = (int)(j >> 6);
        int c  = (int)(j & 63) * 2;   // even column in [0,128)
        int e  = c >> 4;
        int r  = c & 15;              // even -> r, r+1 within same expert row
        float2 v = *(const float2*)(Bm + ((size_t)e * DOUT + o) * 16 + r);
        *(uint32_t*)(g_wf + (size_t)o * KCAT + DIN + c) = pack_h2(v.x, v.y);
    }
}

// ---------------------------------------------------------------------------
// Host launcher — 3 launches, single stream (proven schedule):
//   prep -> h-GEMM(+routing) -> main GEMM.
// ---------------------------------------------------------------------------
constexpr int SMEM_MAIN = 2 * (128 + 256) * PITCH;  // 208896
constexpr int SMEM_H    = 2 * (64 + 128) * PITCH;   // 104448

extern "C" void kernel_launch(void* const* d_in, const int* in_sizes, int n_in,
                              void* d_out, int out_size) {
    const float* x    = (const float*)d_in[0];
    const float* Wb   = (const float*)d_in[1];
    const float* bias = (const float*)d_in[2];
    const float* Wr   = (const float*)d_in[3];
    const float* A    = (const float*)d_in[4];
    const float* Bm   = (const float*)d_in[5];
    float* out = (float*)d_out;

    void *p_xf, *p_wf, *p_af;
    cudaGetSymbolAddress(&p_xf, g_xf);
    cudaGetSymbolAddress(&p_wf, g_wf);
    cudaGetSymbolAddress(&p_af, g_af);

    static bool attr_set = false;
    if (!attr_set) {
        cudaFuncSetAttribute(gemm_mma<KCAT, 128, 256, 0>,
                             cudaFuncAttributeMaxDynamicSharedMemorySize, SMEM_MAIN);
        cudaFuncSetAttribute(gemm_mma<DIN, 64, 128, 1>,
                             cudaFuncAttributeMaxDynamicSharedMemorySize, SMEM_H);
        attr_set = true;
    }

    // 1) prep: x->fp16 + router logits (2 tok/warp), Wb/A/Bflat -> fp16
    {
        long long wtotal = (long long)DOUT * (DIN / 8) + (long long)ER * (DIN / 8)
                         + (long long)DOUT * (ER / 2);
        unsigned wb = (unsigned)((wtotal + 255) / 256);
        prep_kernel<<<XB + wb, 256>>>(x, Wr, Wb, A, Bm);
    }

    // 2) h = x @ A^T  fused with routing -> G columns of g_xf
    //    (BM=64 tiles -> 128 CTAs for SM coverage)
    {
        dim3 grid(1, T_TOK / 64);
        gemm_mma<DIN, 64, 128, 1><<<grid, 256, SMEM_H>>>(
            (const __half*)p_xf, (const __half*)p_af,
            nullptr, nullptr, 0, KCAT, DIN);
    }

    // 3) out = [x|G] @ [Wb|Bf]^T + bias   (n-fast CTA order)
    {
        dim3 grid(DOUT / 256, T_TOK / 128);
        gemm_mma<KCAT, 128, 256, 0><<<grid, 256, SMEM_MAIN>>>(
            (const __half*)p_xf, (const __half*)p_wf,
            bias, out, DOUT, KCAT, KCAT);
    }
}

// round 16
// speedup vs baseline: 1.0233x; 1.0039x over previous
#include <cuda_runtime.h>
#include <cuda_fp16.h>
#include <cstdint>
#include <cstddef>

#define T_TOK 8192
#define DIN   4096
#define DOUT  4096
#define NE    8
#define ER    128          // E * R
#define KCAT  4224         // DIN + ER
#define SCALING 2.0f

// ---------------------------------------------------------------------------
// Scratch (device globals; no allocations allowed)
// ---------------------------------------------------------------------------
__device__ __align__(128) __half g_xf[(size_t)T_TOK * KCAT];
__device__ __align__(128) __half g_wf[(size_t)DOUT * KCAT];
__device__ __align__(128) __half g_af[(size_t)ER * DIN];
__device__ float g_logits[(size_t)T_TOK * NE];

// ---------------------------------------------------------------------------
// PTX primitives (baseline sm_80+)
// ---------------------------------------------------------------------------
__device__ __forceinline__ uint32_t smem_u32(const void* p) {
    uint32_t a;
    asm("{ .reg .u64 t; cvta.to.shared.u64 t, %1; cvt.u32.u64 %0, t; }"
        : "=r"(a) : "l"(p));
    return a;
}
__device__ __forceinline__ void cp16(uint32_t s, const void* g) {
    asm volatile("cp.async.cg.shared.global [%0], [%1], 16;" :: "r"(s), "l"(g));
}
#define CP_COMMIT() asm volatile("cp.async.commit_group;" ::: "memory")
#define CP_WAIT(n)  asm volatile("cp.async.wait_group %0;" :: "n"(n) : "memory")

__device__ __forceinline__ void ldsm4(uint32_t* r, uint32_t addr) {
    asm volatile("ldmatrix.sync.aligned.m8n8.x4.shared.b16 {%0,%1,%2,%3}, [%4];"
                 : "=r"(r[0]), "=r"(r[1]), "=r"(r[2]), "=r"(r[3]) : "r"(addr));
}
__device__ __forceinline__ void mma16816(float* d, const uint32_t* a,
                                         const uint32_t* b) {
    asm volatile(
        "mma.sync.aligned.m16n8k16.row.col.f32.f16.f16.f32 "
        "{%0,%1,%2,%3}, {%4,%5,%6,%7}, {%8,%9}, {%0,%1,%2,%3};"
        : "+f"(d[0]), "+f"(d[1]), "+f"(d[2]), "+f"(d[3])
        : "r"(a[0]), "r"(a[1]), "r"(a[2]), "r"(a[3]), "r"(b[0]), "r"(b[1]));
}

__device__ __forceinline__ uint32_t pack_h2(float a, float b) {
    __half2 h;
    h.x = __float2half_rn(a);
    h.y = __float2half_rn(b);
    return *(const uint32_t*)&h;
}

// ---------------------------------------------------------------------------
// fp16 GEMM: C[M,N] = A @ B^T. Block tile BM x BN, 8 warps.
//   BM=128: warps 2x4, warp tile 64 x BN/4.
//   BM=64 : warps 1x8, warp tile 64 x BN/8.
// BK = 128 halves, 2-stage cp.async, register double-buffered fragments,
// two barriers per chunk (canonical cp.async visibility pattern).
// Smem pitch 272 B: conflict-free for cp.async stores and ldmatrix reads.
// blockIdx.x = n-tile (fast), blockIdx.y = m-tile (A-tile reuse in a wave).
// EPI 0: +bias, fp32 C.   EPI 1: MoE routing epilogue -> fp16 G cols of g_xf.
// ---------------------------------------------------------------------------
#define PITCH 272

template <int K_TOT, int BM, int BN, int EPI>
__global__ void __launch_bounds__(256, 1)
gemm_mma(const __half* __restrict__ A, const __half* __restrict__ B,
         const float* __restrict__ bias, float* __restrict__ C,
         int ldc, int lda, int ldb) {
    constexpr int NCH     = K_TOT / 128;
    constexpr int ROWS    = BM + BN;
    constexpr int STAGE_B = ROWS * PITCH;
    constexpr int MW      = BM / 64;             // m-warps (1 or 2)
    constexpr int WN      = BN / (8 / MW);       // warp n-extent
    constexpr int NP      = WN / 16;             // B ldsm4 per k16
    constexpr int LPT     = ROWS / 16;           // cp16 per thread per stage

    extern __shared__ char sm[];
    const uint32_t base = smem_u32(sm);

    const int tid  = threadIdx.x;
    const int wid  = tid >> 5;
    const int lane = tid & 31;
    const int bm = blockIdx.y * BM;    // m-tile on slow axis
    const int bn = blockIdx.x * BN;    // n-tile on fast axis
    const int wm = (wid % MW) * 64;
    const int wn = (wid / MW) * WN;

    auto stage_load = [&](int c, int s) {
        const int kk = c * 128;
        const uint32_t sb = base + s * STAGE_B;
#pragma unroll
        for (int i = 0; i < LPT; ++i) {
            int idx  = tid + i * 256;
            int row  = idx >> 4;
            int part = idx & 15;
            const __half* g = (row < BM)
                ? A + (size_t)(bm + row) * lda + kk + part * 8
                : B + (size_t)(bn + row - BM) * ldb + kk + part * 8;
            cp16(sb + row * PITCH + part * 16, g);
        }
        CP_COMMIT();
    };

    float acc[4][2 * NP][4];
#pragma unroll
    for (int i = 0; i < 4; i++)
#pragma unroll
        for (int j = 0; j < 2 * NP; j++)
#pragma unroll
            for (int k = 0; k < 4; k++) acc[i][j][k] = 0.f;

    stage_load(0, 0);
    stage_load(1, 1);

    const uint32_t a_off = (wm + (lane & 15)) * PITCH + (lane >> 4) * 16;
    const uint32_t b_row = wn + (lane & 7) + ((lane >> 4) & 1) * 8;
    const uint32_t b_off = b_row * PITCH + ((lane >> 3) & 1) * 16;

    uint32_t aF[2][4][4];
    uint32_t bF[2][NP][4];

    for (int c = 0; c < NCH; ++c) {
        const int s = c & 1;
        // CP_WAIT certifies this thread's chunk-c group; the barrier makes
        // every thread's chunk-c data visible to every warp.
        CP_WAIT(1);
        __syncthreads();

        const uint32_t sA = base + s * STAGE_B;
        const uint32_t sB = sA + BM * PITCH;

        // prime ks=0 frags
#pragma unroll
        for (int mf = 0; mf < 4; ++mf)
            ldsm4(aF[0][mf], sA + a_off + mf * (16 * PITCH));
#pragma unroll
        for (int p = 0; p < NP; ++p)
            ldsm4(bF[0][p], sB + b_off + p * (16 * PITCH));

#pragma unroll
        for (int ks = 0; ks < 8; ++ks) {
            const int cur = ks & 1, nxt = cur ^ 1;
            if (ks < 7) {
#pragma unroll
                for (int mf = 0; mf < 4; ++mf)
                    ldsm4(aF[nxt][mf], sA + a_off + mf * (16 * PITCH) + (ks + 1) * 32);
#pragma unroll
                for (int p = 0; p < NP; ++p)
                    ldsm4(bF[nxt][p], sB + b_off + p * (16 * PITCH) + (ks + 1) * 32);
            }
#pragma unroll
            for (int mf = 0; mf < 4; ++mf)
#pragma unroll
                for (int p = 0; p < NP; ++p) {
                    mma16816(acc[mf][2 * p + 0], aF[cur][mf], &bF[cur][p][0]);
                    mma16816(acc[mf][2 * p + 1], aF[cur][mf], &bF[cur][p][2]);
                }
        }

        // all warps done reading stage s -> safe to overwrite with chunk c+2
        __syncthreads();
        if (c + 2 < NCH) stage_load(c + 2, s);
        else CP_COMMIT();   // keep one commit per iteration (wait invariant)
    }

    const int row0 = wm + (lane >> 2);
    const int col0 = wn + (lane & 3) * 2;

    if (EPI == 0) {
        // bias + fp32 store
#pragma unroll
        for (int mf = 0; mf < 4; ++mf) {
#pragma unroll
            for (int r8 = 0; r8 < 2; ++r8) {
                int row = bm + row0 + mf * 16 + r8 * 8;
                float* Cr = C + (size_t)row * ldc;
#pragma unroll
                for (int nf = 0; nf < 2 * NP; ++nf) {
                    int col = bn + col0 + nf * 8;
                    float2 v;
                    v.x = acc[mf][nf][r8 * 2 + 0];
                    v.y = acc[mf][nf][r8 * 2 + 1];
                    v.x += bias[col]; v.y += bias[col + 1];
                    *(float2*)(Cr + col) = v;
                }
            }
        }
    } else {
        // Routing epilogue: h -> weighted fp16 G columns of g_xf.
        __shared__ float s_w1[BM], s_w2[BM];
        __shared__ int   s_i1[BM], s_i2[BM];
        __syncthreads();
        if (tid < BM) {
            const int t = bm + tid;
            float l[NE];
#pragma unroll
            for (int e = 0; e < NE; ++e) l[e] = g_logits[(size_t)t * NE + e];
            float best = -1e30f; int i1 = 0;
#pragma unroll
            for (int e = 0; e < NE; ++e)
                if (l[e] > best) { best = l[e]; i1 = e; }
            float second = -1e30f; int i2 = 0;
#pragma unroll
            for (int e = 0; e < NE; ++e) {
                if (e == i1) continue;
                if (l[e] > second) { second = l[e]; i2 = e; }
            }
            float r  = expf(second - best);
            float w1 = 1.0f / (1.0f + r);
            s_w1[tid] = SCALING * w1;
            s_w2[tid] = SCALING * r * w1;
            s_i1[tid] = i1;
            s_i2[tid] = i2;
        }
        __syncthreads();
#pragma unroll
        for (int mf = 0; mf < 4; ++mf) {
#pragma unroll
            for (int r8 = 0; r8 < 2; ++r8) {
                int rl = row0 + mf * 16 + r8 * 8;
                int t  = bm + rl;
                float sw1 = s_w1[rl], sw2 = s_w2[rl];
                int i1 = s_i1[rl], i2 = s_i2[rl];
                __half* dst = g_xf + (size_t)t * KCAT + DIN;
#pragma unroll
                for (int nf = 0; nf < 2 * NP; ++nf) {
                    int col = col0 + nf * 8;  // 0..127, even
                    int e = col >> 4;
                    float m = (e == i1) ? sw1 : ((e == i2) ? sw2 : 0.f);
                    __half2 hv;
                    hv.x = __float2half_rn(m * acc[mf][nf][r8 * 2 + 0]);
                    hv.y = __float2half_rn(m * acc[mf][nf][r8 * 2 + 1]);
                    *(__half2*)(dst + col) = hv;
                }
            }
        }
    }
}

// ---------------------------------------------------------------------------
// Merged prep kernel (single launch):
//   blocks [0, XB)   : x fp32->fp16 into g_xf[:, 0:4096) + router logits.
//                      TWO tokens per warp (proven R12 shape, ~54 regs).
//   blocks [XB, ...) : Wb -> g_wf[:, 0:4096), A -> g_af — 16 floats/thread
//                      (4 independent LDG.128 -> MLP=4 covers DRAM latency),
//                      Bm -> g_wf[:, 4096:4224) (half2 pairs)
// ---------------------------------------------------------------------------
#define TPW 2
#define XB  (T_TOK / (8 * TPW))   // 512 blocks

__global__ void __launch_bounds__(256)
prep_kernel(const float* __restrict__ x, const float* __restrict__ Wr,
            const float* __restrict__ Wb, const float* __restrict__ A,
            const float* __restrict__ Bm) {
    if (blockIdx.x < XB) {
        const int wid  = threadIdx.x >> 5;
        const int lane = threadIdx.x & 31;
        const int t0 = (blockIdx.x * 8 + wid) * TPW;
        const float* xr0 = x + (size_t)t0 * DIN;
        const float* xr1 = xr0 + DIN;
        __half* xo0 = g_xf + (size_t)t0 * KCAT;
        __half* xo1 = xo0 + KCAT;

        float acc0[NE], acc1[NE];
#pragma unroll
        for (int e = 0; e < NE; ++e) { acc0[e] = 0.f; acc1[e] = 0.f; }

#pragma unroll 2
        for (int i = 0; i < 32; ++i) {
            int off = i * 128 + lane * 4;
            float4 w[NE];
#pragma unroll
            for (int e = 0; e < NE; ++e)
                w[e] = *(const float4*)(Wr + (size_t)e * DIN + off);

            float4 v0 = *(const float4*)(xr0 + off);
            float4 v1 = *(const float4*)(xr1 + off);
            uint2 p0, p1;
            p0.x = pack_h2(v0.x, v0.y); p0.y = pack_h2(v0.z, v0.w);
            p1.x = pack_h2(v1.x, v1.y); p1.y = pack_h2(v1.z, v1.w);
            *(uint2*)(xo0 + off) = p0;
            *(uint2*)(xo1 + off) = p1;
#pragma unroll
            for (int e = 0; e < NE; ++e) {
                acc0[e] += v0.x * w[e].x + v0.y * w[e].y
                         + v0.z * w[e].z + v0.w * w[e].w;
                acc1[e] += v1.x * w[e].x + v1.y * w[e].y
                         + v1.z * w[e].z + v1.w * w[e].w;
            }
        }
#pragma unroll
        for (int e = 0; e < NE; ++e) {
#pragma unroll
            for (int off = 16; off > 0; off >>= 1) {
                acc0[e] += __shfl_xor_sync(0xffffffffu, acc0[e], off);
                acc1[e] += __shfl_xor_sync(0xffffffffu, acc1[e], off);
            }
        }
        if (lane == 0) {
#pragma unroll
            for (int e = 0; e < NE; ++e) {
                g_logits[(size_t)t0 * NE + e]       = acc0[e];
                g_logits[(size_t)(t0 + 1) * NE + e] = acc1[e];
            }
        }
        return;
    }

    // weight-prep part: 16-float groups (4x LDG.128 in flight per thread)
    const long long N1 = (long long)DOUT * (DIN / 16);  // Wb groups
    const long long N2 = (long long)ER * (DIN / 16);    // A groups
    const long long N3 = (long long)DOUT * (ER / 2);    // Bflat half2
    long long i = (long long)(blockIdx.x - XB) * 256 + threadIdx.x;
    if (i < N1 + N2) {
        const float* src;
        __half* dst;
        if (i < N1) {
            long long r = i / (DIN / 16);
            int c16 = (int)(i % (DIN / 16));
            src = Wb + r * DIN + 16 * c16;
            dst = g_wf + r * KCAT + 16 * c16;
        } else {
            long long j = i - N1;
            src = A + 16 * j;
            dst = g_af + 16 * j;
        }
        // 4 independent loads issued back-to-back (MLP=4)
        float4 v0 = *(const float4*)(src);
        float4 v1 = *(const float4*)(src + 4);
        float4 v2 = *(const float4*)(src + 8);
        float4 v3 = *(const float4*)(src + 12);
        uint4 pa, pb;
        pa.x = pack_h2(v0.x, v0.y); pa.y = pack_h2(v0.z, v0.w);
        pa.z = pack_h2(v1.x, v1.y); pa.w = pack_h2(v1.z, v1.w);
        pb.x = pack_h2(v2.x, v2.y); pb.y = pack_h2(v2.z, v2.w);
        pb.z = pack_h2(v3.x, v3.y); pb.w = pack_h2(v3.z, v3.w);
        *(uint4*)(dst) = pa;
        *(uint4*)(dst + 8) = pb;
    } else if (i < N1 + N2 + N3) {
        long long j = i - N1 - N2;
        int o  = (int)(j >> 6);
        int c  = (int)(j & 63) * 2;   // even column in [0,128)
        int e  = c >> 4;
        int r  = c & 15;              // even -> r, r+1 within same expert row
        float2 v = *(const float2*)(Bm + ((size_t)e * DOUT + o) * 16 + r);
        *(uint32_t*)(g_wf + (size_t)o * KCAT + DIN + c) = pack_h2(v.x, v.y);
    }
}

// ---------------------------------------------------------------------------
// Host launcher — 3 launches, single stream (proven schedule):
//   prep -> h-GEMM(+routing) -> main GEMM.
// ---------------------------------------------------------------------------
constexpr int SMEM_MAIN = 2 * (128 + 256) * PITCH;  // 208896
constexpr int SMEM_H    = 2 * (64 + 128) * PITCH;   // 104448

extern "C" void kernel_launch(void* const* d_in, const int* in_sizes, int n_in,
                              void* d_out, int out_size) {
    const float* x    = (const float*)d_in[0];
    const float* Wb   = (const float*)d_in[1];
    const float* bias = (const float*)d_in[2];
    const float* Wr   = (const float*)d_in[3];
    const float* A    = (const float*)d_in[4];
    const float* Bm   = (const float*)d_in[5];
    float* out = (float*)d_out;

    void *p_xf, *p_wf, *p_af;
    cudaGetSymbolAddress(&p_xf, g_xf);
    cudaGetSymbolAddress(&p_wf, g_wf);
    cudaGetSymbolAddress(&p_af, g_af);

    static bool attr_set = false;
    if (!attr_set) {
        cudaFuncSetAttribute(gemm_mma<KCAT, 128, 256, 0>,
                             cudaFuncAttributeMaxDynamicSharedMemorySize, SMEM_MAIN);
        cudaFuncSetAttribute(gemm_mma<DIN, 64, 128, 1>,
                             cudaFuncAttributeMaxDynamicSharedMemorySize, SMEM_H);
        attr_set = true;
    }

    // 1) prep: x->fp16 + router logits (2 tok/warp), Wb/A/Bflat -> fp16
    {
        long long wtotal = (long long)DOUT * (DIN / 16) + (long long)ER * (DIN / 16)
                         + (long long)DOUT * (ER / 2);
        unsigned wb = (unsigned)((wtotal + 255) / 256);
        prep_kernel<<<XB + wb, 256>>>(x, Wr, Wb, A, Bm);
    }

    // 2) h = x @ A^T  fused with routing -> G columns of g_xf
    //    (BM=64 tiles -> 128 CTAs for SM coverage)
    {
        dim3 grid(1, T_TOK / 64);
        gemm_mma<DIN, 64, 128, 1><<<grid, 256, SMEM_H>>>(
            (const __half*)p_xf, (const __half*)p_af,
            nullptr, nullptr, 0, KCAT, DIN);
    }

    // 3) out = [x|G] @ [Wb|Bf]^T + bias   (n-fast CTA order)
    {
        dim3 grid(DOUT / 256, T_TOK / 128);
        gemm_mma<KCAT, 128, 256, 0><<<grid, 256, SMEM_MAIN>>>(
            (const __half*)p_xf, (const __half*)p_wf,
            bias, out, DOUT, KCAT, KCAT);
    }
}

// round 17
// speedup vs baseline: 1.0772x; 1.0527x over previous
#include <cuda_runtime.h>
#include <cuda_fp16.h>
#include <cstdint>
#include <cstddef>

#define T_TOK 8192
#define DIN   4096
#define DOUT  4096
#define NE    8
#define ER    128          // E * R
#define KCAT  4224         // DIN + ER
#define SCALING 2.0f

// ---------------------------------------------------------------------------
// Scratch (device globals; no allocations allowed)
// ---------------------------------------------------------------------------
__device__ __align__(128) __half g_xf[(size_t)T_TOK * KCAT];
__device__ __align__(128) __half g_wf[(size_t)DOUT * KCAT];
__device__ __align__(128) __half g_af[(size_t)ER * DIN];
__device__ float g_logits[(size_t)T_TOK * NE];

// ---------------------------------------------------------------------------
// PTX primitives (baseline sm_80+)
// ---------------------------------------------------------------------------
__device__ __forceinline__ uint32_t smem_u32(const void* p) {
    uint32_t a;
    asm("{ .reg .u64 t; cvta.to.shared.u64 t, %1; cvt.u32.u64 %0, t; }"
        : "=r"(a) : "l"(p));
    return a;
}
__device__ __forceinline__ void cp16(uint32_t s, const void* g) {
    asm volatile("cp.async.cg.shared.global [%0], [%1], 16;" :: "r"(s), "l"(g));
}
#define CP_COMMIT() asm volatile("cp.async.commit_group;" ::: "memory")
#define CP_WAIT(n)  asm volatile("cp.async.wait_group %0;" :: "n"(n) : "memory")

__device__ __forceinline__ void ldsm4(uint32_t* r, uint32_t addr) {
    asm volatile("ldmatrix.sync.aligned.m8n8.x4.shared.b16 {%0,%1,%2,%3}, [%4];"
                 : "=r"(r[0]), "=r"(r[1]), "=r"(r[2]), "=r"(r[3]) : "r"(addr));
}
__device__ __forceinline__ void mma16816(float* d, const uint32_t* a,
                                         const uint32_t* b) {
    asm volatile(
        "mma.sync.aligned.m16n8k16.row.col.f32.f16.f16.f32 "
        "{%0,%1,%2,%3}, {%4,%5,%6,%7}, {%8,%9}, {%0,%1,%2,%3};"
        : "+f"(d[0]), "+f"(d[1]), "+f"(d[2]), "+f"(d[3])
        : "r"(a[0]), "r"(a[1]), "r"(a[2]), "r"(a[3]), "r"(b[0]), "r"(b[1]));
}

__device__ __forceinline__ uint32_t pack_h2(float a, float b) {
    __half2 h;
    h.x = __float2half_rn(a);
    h.y = __float2half_rn(b);
    return *(const uint32_t*)&h;
}

// ---------------------------------------------------------------------------
// fp16 GEMM: C[M,N] = A @ B^T. Block tile BM x BN, 8 warps, BK template.
//   BM=128: warps 2x4, warp tile 64 x BN/4.
//   BM=64 : warps 1x8, warp tile 64 x BN/8.
// 2-stage cp.async, two barriers per chunk (canonical visibility pattern).
// Smem pitch = BK*2+16 bytes (16B pad): conflict-free for cp.async stores and
// ldmatrix reads (row stride mod 32 banks covers all banks across 8 rows).
// OCC = min CTAs/SM hint: OCC=2 gives two independent CTAs per SM whose
// barrier/prime phases interleave, keeping the tensor pipe fed.
// Frags single-buffered when OCC=2 (fits 128 regs); OCC=1 path unchanged.
// EPI 0: +bias, fp32 C.   EPI 1: MoE routing epilogue -> fp16 G cols of g_xf.
// ---------------------------------------------------------------------------
template <int K_TOT, int BM, int BN, int BK, int EPI, int OCC>
__global__ void __launch_bounds__(256, OCC)
gemm_mma(const __half* __restrict__ A, const __half* __restrict__ B,
         const float* __restrict__ bias, float* __restrict__ C,
         int ldc, int lda, int ldb) {
    constexpr int PITCH   = BK * 2 + 16;
    constexpr int NCH     = K_TOT / BK;
    constexpr int KS      = BK / 16;             // k16 steps per chunk
    constexpr int ROWS    = BM + BN;
    constexpr int STAGE_B = ROWS * PITCH;
    constexpr int MW      = BM / 64;             // m-warps (1 or 2)
    constexpr int WN      = BN / (8 / MW);       // warp n-extent
    constexpr int NP      = WN / 16;             // B ldsm4 per k16
    constexpr int PPR     = BK / 8;              // cp16 per row
    constexpr int LPT     = ROWS * PPR / 256;    // cp16 per thread per stage

    extern __shared__ char sm[];
    const uint32_t base = smem_u32(sm);

    const int tid  = threadIdx.x;
    const int wid  = tid >> 5;
    const int lane = tid & 31;
    const int bm = blockIdx.y * BM;    // m-tile on slow axis
    const int bn = blockIdx.x * BN;    // n-tile on fast axis
    const int wm = (wid % MW) * 64;
    const int wn = (wid / MW) * WN;

    auto stage_load = [&](int c, int s) {
        const int kk = c * BK;
        const uint32_t sb = base + s * STAGE_B;
#pragma unroll
        for (int i = 0; i < LPT; ++i) {
            int idx  = tid + i * 256;
            int row  = idx / PPR;
            int part = idx % PPR;
            const __half* g = (row < BM)
                ? A + (size_t)(bm + row) * lda + kk + part * 8
                : B + (size_t)(bn + row - BM) * ldb + kk + part * 8;
            cp16(sb + row * PITCH + part * 16, g);
        }
        CP_COMMIT();
    };

    float acc[4][2 * NP][4];
#pragma unroll
    for (int i = 0; i < 4; i++)
#pragma unroll
        for (int j = 0; j < 2 * NP; j++)
#pragma unroll
            for (int k = 0; k < 4; k++) acc[i][j][k] = 0.f;

    stage_load(0, 0);
    stage_load(1, 1);

    const uint32_t a_off = (wm + (lane & 15)) * PITCH + (lane >> 4) * 16;
    const uint32_t b_row = wn + (lane & 7) + ((lane >> 4) & 1) * 8;
    const uint32_t b_off = b_row * PITCH + ((lane >> 3) & 1) * 16;

    for (int c = 0; c < NCH; ++c) {
        const int s = c & 1;
        // CP_WAIT certifies this thread's chunk-c group; the barrier makes
        // every thread's chunk-c data visible to every warp.
        CP_WAIT(1);
        __syncthreads();

        const uint32_t sA = base + s * STAGE_B;
        const uint32_t sB = sA + BM * PITCH;

#pragma unroll
        for (int ks = 0; ks < KS; ++ks) {
            uint32_t aF[4][4];
            uint32_t bF[NP][4];
#pragma unroll
            for (int mf = 0; mf < 4; ++mf)
                ldsm4(aF[mf], sA + a_off + mf * (16 * PITCH) + ks * 32);
#pragma unroll
            for (int p = 0; p < NP; ++p)
                ldsm4(bF[p], sB + b_off + p * (16 * PITCH) + ks * 32);
#pragma unroll
            for (int mf = 0; mf < 4; ++mf)
#pragma unroll
                for (int p = 0; p < NP; ++p) {
                    mma16816(acc[mf][2 * p + 0], aF[mf], &bF[p][0]);
                    mma16816(acc[mf][2 * p + 1], aF[mf], &bF[p][2]);
                }
        }

        // all warps done reading stage s -> safe to overwrite with chunk c+2
        __syncthreads();
        if (c + 2 < NCH) stage_load(c + 2, s);
        else CP_COMMIT();   // keep one commit per iteration (wait invariant)
    }

    const int row0 = wm + (lane >> 2);
    const int col0 = wn + (lane & 3) * 2;

    if (EPI == 0) {
        // bias + fp32 store
#pragma unroll
        for (int mf = 0; mf < 4; ++mf) {
#pragma unroll
            for (int r8 = 0; r8 < 2; ++r8) {
                int row = bm + row0 + mf * 16 + r8 * 8;
                float* Cr = C + (size_t)row * ldc;
#pragma unroll
                for (int nf = 0; nf < 2 * NP; ++nf) {
                    int col = bn + col0 + nf * 8;
                    float2 v;
                    v.x = acc[mf][nf][r8 * 2 + 0];
                    v.y = acc[mf][nf][r8 * 2 + 1];
                    v.x += bias[col]; v.y += bias[col + 1];
                    *(float2*)(Cr + col) = v;
                }
            }
        }
    } else {
        // Routing epilogue: h -> weighted fp16 G columns of g_xf.
        __shared__ float s_w1[BM], s_w2[BM];
        __shared__ int   s_i1[BM], s_i2[BM];
        __syncthreads();
        if (tid < BM) {
            const int t = bm + tid;
            float l[NE];
#pragma unroll
            for (int e = 0; e < NE; ++e) l[e] = g_logits[(size_t)t * NE + e];
            float best = -1e30f; int i1 = 0;
#pragma unroll
            for (int e = 0; e < NE; ++e)
                if (l[e] > best) { best = l[e]; i1 = e; }
            float second = -1e30f; int i2 = 0;
#pragma unroll
            for (int e = 0; e < NE; ++e) {
                if (e == i1) continue;
                if (l[e] > second) { second = l[e]; i2 = e; }
            }
            float r  = expf(second - best);
            float w1 = 1.0f / (1.0f + r);
            s_w1[tid] = SCALING * w1;
            s_w2[tid] = SCALING * r * w1;
            s_i1[tid] = i1;
            s_i2[tid] = i2;
        }
        __syncthreads();
#pragma unroll
        for (int mf = 0; mf < 4; ++mf) {
#pragma unroll
            for (int r8 = 0; r8 < 2; ++r8) {
                int rl = row0 + mf * 16 + r8 * 8;
                int t  = bm + rl;
                float sw1 = s_w1[rl], sw2 = s_w2[rl];
                int i1 = s_i1[rl], i2 = s_i2[rl];
                __half* dst = g_xf + (size_t)t * KCAT + DIN;
#pragma unroll
                for (int nf = 0; nf < 2 * NP; ++nf) {
                    int col = col0 + nf * 8;  // 0..127, even
                    int e = col >> 4;
                    float m = (e == i1) ? sw1 : ((e == i2) ? sw2 : 0.f);
                    __half2 hv;
                    hv.x = __float2half_rn(m * acc[mf][nf][r8 * 2 + 0]);
                    hv.y = __float2half_rn(m * acc[mf][nf][r8 * 2 + 1]);
                    *(__half2*)(dst + col) = hv;
                }
            }
        }
    }
}

// ---------------------------------------------------------------------------
// Merged prep kernel (single launch, R16-proven):
//   blocks [0, XB)   : x fp32->fp16 + router logits, 2 tokens/warp.
//   blocks [XB, ...) : Wb/A -> fp16 (16 floats/thread, MLP=4), Bflat half2.
// ---------------------------------------------------------------------------
#define TPW 2
#define XB  (T_TOK / (8 * TPW))   // 512 blocks

__global__ void __launch_bounds__(256)
prep_kernel(const float* __restrict__ x, const float* __restrict__ Wr,
            const float* __restrict__ Wb, const float* __restrict__ A,
            const float* __restrict__ Bm) {
    if (blockIdx.x < XB) {
        const int wid  = threadIdx.x >> 5;
        const int lane = threadIdx.x & 31;
        const int t0 = (blockIdx.x * 8 + wid) * TPW;
        const float* xr0 = x + (size_t)t0 * DIN;
        const float* xr1 = xr0 + DIN;
        __half* xo0 = g_xf + (size_t)t0 * KCAT;
        __half* xo1 = xo0 + KCAT;

        float acc0[NE], acc1[NE];
#pragma unroll
        for (int e = 0; e < NE; ++e) { acc0[e] = 0.f; acc1[e] = 0.f; }

#pragma unroll 2
        for (int i = 0; i < 32; ++i) {
            int off = i * 128 + lane * 4;
            float4 w[NE];
#pragma unroll
            for (int e = 0; e < NE; ++e)
                w[e] = *(const float4*)(Wr + (size_t)e * DIN + off);

            float4 v0 = *(const float4*)(xr0 + off);
            float4 v1 = *(const float4*)(xr1 + off);
            uint2 p0, p1;
            p0.x = pack_h2(v0.x, v0.y); p0.y = pack_h2(v0.z, v0.w);
            p1.x = pack_h2(v1.x, v1.y); p1.y = pack_h2(v1.z, v1.w);
            *(uint2*)(xo0 + off) = p0;
            *(uint2*)(xo1 + off) = p1;
#pragma unroll
            for (int e = 0; e < NE; ++e) {
                acc0[e] += v0.x * w[e].x + v0.y * w[e].y
                         + v0.z * w[e].z + v0.w * w[e].w;
                acc1[e] += v1.x * w[e].x + v1.y * w[e].y
                         + v1.z * w[e].z + v1.w * w[e].w;
            }
        }
#pragma unroll
        for (int e = 0; e < NE; ++e) {
#pragma unroll
            for (int off = 16; off > 0; off >>= 1) {
                acc0[e] += __shfl_xor_sync(0xffffffffu, acc0[e], off);
                acc1[e] += __shfl_xor_sync(0xffffffffu, acc1[e], off);
            }
        }
        if (lane == 0) {
#pragma unroll
            for (int e = 0; e < NE; ++e) {
                g_logits[(size_t)t0 * NE + e]       = acc0[e];
                g_logits[(size_t)(t0 + 1) * NE + e] = acc1[e];
            }
        }
        return;
    }

    // weight-prep part: 16-float groups (4x LDG.128 in flight per thread)
    const long long N1 = (long long)DOUT * (DIN / 16);  // Wb groups
    const long long N2 = (long long)ER * (DIN / 16);    // A groups
    const long long N3 = (long long)DOUT * (ER / 2);    // Bflat half2
    long long i = (long long)(blockIdx.x - XB) * 256 + threadIdx.x;
    if (i < N1 + N2) {
        const float* src;
        __half* dst;
        if (i < N1) {
            long long r = i / (DIN / 16);
            int c16 = (int)(i % (DIN / 16));
            src = Wb + r * DIN + 16 * c16;
            dst = g_wf + r * KCAT + 16 * c16;
        } else {
            long long j = i - N1;
            src = A + 16 * j;
            dst = g_af + 16 * j;
        }
        float4 v0 = *(const float4*)(src);
        float4 v1 = *(const float4*)(src + 4);
        float4 v2 = *(const float4*)(src + 8);
        float4 v3 = *(const float4*)(src + 12);
        uint4 pa, pb;
        pa.x = pack_h2(v0.x, v0.y); pa.y = pack_h2(v0.z, v0.w);
        pa.z = pack_h2(v1.x, v1.y); pa.w = pack_h2(v1.z, v1.w);
        pb.x = pack_h2(v2.x, v2.y); pb.y = pack_h2(v2.z, v2.w);
        pb.z = pack_h2(v3.x, v3.y); pb.w = pack_h2(v3.z, v3.w);
        *(uint4*)(dst) = pa;
        *(uint4*)(dst + 8) = pb;
    } else if (i < N1 + N2 + N3) {
        long long j = i - N1 - N2;
        int o  = (int)(j >> 6);
        int c  = (int)(j & 63) * 2;   // even column in [0,128)
        int e  = c >> 4;
        int r  = c & 15;
        float2 v = *(const float2*)(Bm + ((size_t)e * DOUT + o) * 16 + r);
        *(uint32_t*)(g_wf + (size_t)o * KCAT + DIN + c) = pack_h2(v.x, v.y);
    }
}

// ---------------------------------------------------------------------------
// Host launcher — 3 launches, single stream:
//   prep -> h-GEMM(+routing) -> main GEMM (128x128 tiles, 2 CTAs/SM).
// ---------------------------------------------------------------------------
constexpr int SMEM_MAIN = 2 * (128 + 128) * 144;   // 73728 (BK=64, OCC=2)
constexpr int SMEM_H    = 2 * (64 + 128) * 272;    // 104448 (BK=128, OCC=1)

extern "C" void kernel_launch(void* const* d_in, const int* in_sizes, int n_in,
                              void* d_out, int out_size) {
    const float* x    = (const float*)d_in[0];
    const float* Wb   = (const float*)d_in[1];
    const float* bias = (const float*)d_in[2];
    const float* Wr   = (const float*)d_in[3];
    const float* A    = (const float*)d_in[4];
    const float* Bm   = (const float*)d_in[5];
    float* out = (float*)d_out;

    void *p_xf, *p_wf, *p_af;
    cudaGetSymbolAddress(&p_xf, g_xf);
    cudaGetSymbolAddress(&p_wf, g_wf);
    cudaGetSymbolAddress(&p_af, g_af);

    static bool attr_set = false;
    if (!attr_set) {
        cudaFuncSetAttribute(gemm_mma<KCAT, 128, 128, 64, 0, 2>,
                             cudaFuncAttributeMaxDynamicSharedMemorySize, SMEM_MAIN);
        cudaFuncSetAttribute(gemm_mma<DIN, 64, 128, 128, 1, 1>,
                             cudaFuncAttributeMaxDynamicSharedMemorySize, SMEM_H);
        attr_set = true;
    }

    // 1) prep: x->fp16 + router logits (2 tok/warp), Wb/A/Bflat -> fp16
    {
        long long wtotal = (long long)DOUT * (DIN / 16) + (long long)ER * (DIN / 16)
                         + (long long)DOUT * (ER / 2);
        unsigned wb = (unsigned)((wtotal + 255) / 256);
        prep_kernel<<<XB + wb, 256>>>(x, Wr, Wb, A, Bm);
    }

    // 2) h = x @ A^T  fused with routing -> G columns of g_xf
    {
        dim3 grid(1, T_TOK / 64);
        gemm_mma<DIN, 64, 128, 128, 1, 1><<<grid, 256, SMEM_H>>>(
            (const __half*)p_xf, (const __half*)p_af,
            nullptr, nullptr, 0, KCAT, DIN);
    }

    // 3) out = [x|G] @ [Wb|Bf]^T + bias
    //    (128x128 tiles, BK=64, 2 CTAs/SM -> barrier phases interleave)
    {
        dim3 grid(DOUT / 128, T_TOK / 128);
        gemm_mma<KCAT, 128, 128, 64, 0, 2><<<grid, 256, SMEM_MAIN>>>(
            (const __half*)p_xf, (const __half*)p_wf,
            bias, out, DOUT, KCAT, KCAT);
    }
}